// round 11
// baseline (speedup 1.0000x reference)
#include <cuda_runtime.h>
#include <cuda_fp16.h>
#include <cstdint>
#include <cstddef>

#define BATCH 64
#define INF   1024
#define OUTF  1024
#define NEXP  8
#define HID   8
#define SPLITS 16

// c[e][b] = sum_f att[b,f] * align_conv[f,e]
__device__ float g_c[NEXP * BATCH];
// split-K partials [kz][o][b]  (4 MB static scratch)
__device__ float g_part[SPLITS * OUTF * BATCH];

// ---------------------------------------------------------------------------
// arch-agnostic tensor-core helpers (sm_80+ PTX: valid at target sm_103)
// ---------------------------------------------------------------------------
__device__ __forceinline__ uint32_t smem_u32(const void* p) {
    uint32_t a;
    asm("{ .reg .u64 t; cvta.to.shared.u64 t, %1; cvt.u32.u64 %0, t; }"
        : "=r"(a) : "l"(p));
    return a;
}

__device__ __forceinline__ void ldsm4(uint32_t* r, uint32_t addr) {
    asm volatile("ldmatrix.sync.aligned.m8n8.x4.shared.b16 {%0,%1,%2,%3}, [%4];"
                 : "=r"(r[0]), "=r"(r[1]), "=r"(r[2]), "=r"(r[3]) : "r"(addr));
}

__device__ __forceinline__ void mma16816(float* d, const uint32_t* a,
                                         uint32_t b0, uint32_t b1) {
    asm volatile(
        "mma.sync.aligned.m16n8k16.row.col.f32.f16.f16.f32 "
        "{%0,%1,%2,%3}, {%4,%5,%6,%7}, {%8,%9}, {%0,%1,%2,%3};"
        : "+f"(d[0]), "+f"(d[1]), "+f"(d[2]), "+f"(d[3])
        : "r"(a[0]), "r"(a[1]), "r"(a[2]), "r"(a[3]), "r"(b0), "r"(b1));
}

__device__ __forceinline__ uint32_t h2bits(float a, float b) {
    __half2 h = __floats2half2_rn(a, b);   // low = a, high = b (k-order)
    return *reinterpret_cast<uint32_t*>(&h);
}

__device__ __forceinline__ float tanh_fast(float v) {
    float r;
    asm("tanh.approx.f32 %0, %1;" : "=f"(r) : "f"(v));
    return r;
}

// ---------------------------------------------------------------------------
// Gating: grid 64 (one block per batch sample), 256 threads.
// float4 mean-reduce; tail parallelized over 8 lanes (one per expert).
// Fast-path MUFU: tanh.approx + __expf (err ~1e-5, far under budget).
// ---------------------------------------------------------------------------
__global__ void __launch_bounds__(256) gate_kernel(
    const float* __restrict__ x,
    const float* __restrict__ align_conv,
    const float* __restrict__ W_ih,
    const float* __restrict__ b_ih,
    const float* __restrict__ b_hh,
    const float* __restrict__ W_att,
    const float* __restrict__ b_att)
{
    const int b   = blockIdx.x;
    const int tid = threadIdx.x;
    __shared__ float red[8];

    float4 v = ((const float4*)(x + (size_t)b * INF))[tid];
    float s = (v.x + v.y) + (v.z + v.w);
#pragma unroll
    for (int o = 16; o > 0; o >>= 1) s += __shfl_xor_sync(0xffffffffu, s, o);
    if ((tid & 31) == 0) red[tid >> 5] = s;
    __syncthreads();

    if (tid < 8) {
        float t8 = red[tid];
        t8 += __shfl_xor_sync(0xffu, t8, 1);
        t8 += __shfl_xor_sync(0xffu, t8, 2);
        t8 += __shfl_xor_sync(0xffu, t8, 4);
        const float pooled = t8 * (1.0f / INF);

        const int e = tid;
        float lg = b_att[e];
#pragma unroll
        for (int j = 0; j < HID; j++) {
            float rj = fmaxf(tanh_fast(pooled * W_ih[j] + b_ih[j] + b_hh[j]), 0.f);
            lg += rj * W_att[e * HID + j];
        }
        float mx = lg;
        mx = fmaxf(mx, __shfl_xor_sync(0xffu, mx, 1));
        mx = fmaxf(mx, __shfl_xor_sync(0xffu, mx, 2));
        mx = fmaxf(mx, __shfl_xor_sync(0xffu, mx, 4));
        float p = __expf(lg - mx);
        float ssum = p;
        ssum += __shfl_xor_sync(0xffu, ssum, 1);
        ssum += __shfl_xor_sync(0xffu, ssum, 2);
        ssum += __shfl_xor_sync(0xffu, ssum, 4);
        p /= ssum;

        float c = 0.f;
#pragma unroll
        for (int f = 0; f < NEXP; f++)
            c += __shfl_sync(0xffu, p, f) * align_conv[f * NEXP + e];
        g_c[e * BATCH + b] = c;
    }
}

// ---------------------------------------------------------------------------
// HMMA GEMM: part[kz][o][b] = sum_{i in chunk} w[e,o,i] * (c[b,e]*x[b,i])
//   fp16 operands, fp32 accum (mma.sync m16n8k16).
//   CTA: M=64 (o), N=64 (b); grid = (16 o-tiles, 16 = 8 experts x 2 i-halves)
//   = 256 CTAs (~2/SM: full chip coverage + cross-CTA latency hiding).
//   K=512/CTA in 8 chunks of 64; double-buffered 16KB stages (32KB static).
//   SMEM tiles (fp16): A[o 64][k 64] 8KB + B[b 64][k 64] 8KB, 128B rows,
//   16B-granular XOR swizzle -> conflict-free ldmatrix.
//   Warp tile m32 x n16 (warps: 2 along M x 4 along N).
// ---------------------------------------------------------------------------
#define KC       64
#define NCH      8
#define A_BYTES  8192
#define STG      16384

__global__ void __launch_bounds__(256) gemm_hmma(const float* __restrict__ x,
                                                 const float* __restrict__ w)
{
    __shared__ __align__(16) uint8_t sm[2 * STG];
    const int tid = threadIdx.x;
    const int wid = tid >> 5;
    const int lid = tid & 31;
    const int o0  = blockIdx.x * 64;
    const int kz  = blockIdx.y;
    const int e   = kz >> 1;
    const int i0  = (kz & 1) * 512;

    const float* wbase = w + ((size_t)e << 20) + (size_t)o0 * INF + i0;
    const float* xbase = x + i0;

    const int m0 = (wid & 1) * 32;     // warp M offset
    const int n0 = (wid >> 1) * 16;    // warp N offset

    float d[2][2][4];
#pragma unroll
    for (int i = 0; i < 2; i++)
#pragma unroll
        for (int j = 0; j < 2; j++)
#pragma unroll
            for (int k = 0; k < 4; k++) d[i][j][k] = 0.f;

    // loader: A 4 float4/thread, B 4 float4/thread per chunk
    float cs[4];
#pragma unroll
    for (int r = 0; r < 4; r++)
        cs[r] = g_c[e * BATCH + ((tid + (r << 8)) >> 4)];

    float4 av[4], bv[4];
    const uint32_t smb = smem_u32(sm);

    // ---- prologue: load stage 0 ----
    {
        const float4* ws = (const float4*)wbase;
        const float4* xs = (const float4*)xbase;
#pragma unroll
        for (int r = 0; r < 4; r++) {
            int g = tid + (r << 8);
            av[r] = ws[(g >> 4) * 256 + (g & 15)];
            bv[r] = xs[(g >> 4) * 256 + (g & 15)];
        }
    }

#define STORE_STAGE(sidx) do {                                                 \
    uint8_t* stg = sm + (sidx) * STG;                                          \
    _Pragma("unroll")                                                          \
    for (int r = 0; r < 4; r++) {                                              \
        int g = tid + (r << 8);                                                \
        uint32_t off = (uint32_t)((g >> 4) * 128 + (g & 15) * 8);              \
        off ^= (off >> 3) & 0x70u;                                             \
        uint2 pa; pa.x = h2bits(av[r].x, av[r].y);                             \
        pa.y = h2bits(av[r].z, av[r].w);                                       \
        *(uint2*)(stg + off) = pa;                                             \
        float c4 = cs[r];                                                      \
        uint2 pb; pb.x = h2bits(bv[r].x * c4, bv[r].y * c4);                   \
        pb.y = h2bits(bv[r].z * c4, bv[r].w * c4);                             \
        *(uint2*)(stg + A_BYTES + off) = pb;                                   \
    }                                                                          \
} while (0)

    STORE_STAGE(0);
    __syncthreads();

    for (int kc = 0; kc < NCH; kc++) {
        const int cur = kc & 1;

        if (kc + 1 < NCH) {
            const float4* ws = (const float4*)(wbase + (kc + 1) * KC);
            const float4* xs = (const float4*)(xbase + (kc + 1) * KC);
#pragma unroll
            for (int r = 0; r < 4; r++) {
                int g = tid + (r << 8);
                av[r] = ws[(g >> 4) * 256 + (g & 15)];
                bv[r] = xs[(g >> 4) * 256 + (g & 15)];
            }
        }

        // ---- compute on stage `cur` ----
        const uint32_t sb = smb + cur * STG;
#pragma unroll
        for (int ks = 0; ks < 4; ks++) {
            uint32_t afr[2][4], bfr[4];
#pragma unroll
            for (int mf = 0; mf < 2; mf++) {
                uint32_t row = (uint32_t)(m0 + mf * 16 + (lid & 15));
                uint32_t kg  = (uint32_t)(ks * 2 + (lid >> 4));
                uint32_t off = row * 128 + kg * 16;
                off ^= (off >> 3) & 0x70u;
                ldsm4(afr[mf], sb + off);
            }
            {
                uint32_t nrow = (uint32_t)(n0 + (lid & 7) + ((lid >> 4) << 3));
                uint32_t kg   = (uint32_t)(ks * 2 + ((lid >> 3) & 1));
                uint32_t off  = nrow * 128 + kg * 16;
                off ^= (off >> 3) & 0x70u;
                ldsm4(bfr, sb + A_BYTES + off);
            }
#pragma unroll
            for (int mf = 0; mf < 2; mf++) {
                mma16816(d[mf][0], afr[mf], bfr[0], bfr[1]);
                mma16816(d[mf][1], afr[mf], bfr[2], bfr[3]);
            }
        }

        __syncthreads();
        if (kc + 1 < NCH) {
            STORE_STAGE(cur ^ 1);
            __syncthreads();
        }
    }

    // ---- epilogue: STG.64 partials to g_part[kz][o][b] ----
    float* part = g_part + (size_t)kz * (OUTF * BATCH);
    const int tg = lid >> 2;
    const int tc = (lid & 3) * 2;
#pragma unroll
    for (int mf = 0; mf < 2; mf++) {
#pragma unroll
        for (int nf = 0; nf < 2; nf++) {
            const int ol = m0 + mf * 16 + tg;
            const int bb = n0 + nf * 8 + tc;
            float2 v0; v0.x = d[mf][nf][0]; v0.y = d[mf][nf][1];
            float2 v1; v1.x = d[mf][nf][2]; v1.y = d[mf][nf][3];
            *(float2*)(part + (size_t)(o0 + ol) * BATCH + bb) = v0;
            *(float2*)(part + (size_t)(o0 + ol + 8) * BATCH + bb) = v1;
        }
    }
}

// ---------------------------------------------------------------------------
// Split-K reduce + transpose: y[b][o] = sum_kz part[kz][o][b].
// Coalesced loads (b fastest); 4 MB is L2-resident.
// ---------------------------------------------------------------------------
__global__ void __launch_bounds__(256) reduce_kernel(float* __restrict__ y)
{
    const int gid = blockIdx.x * 256 + threadIdx.x;   // 0..65535
    const int o = gid >> 6;
    const int b = gid & 63;
    const float* p = g_part + (size_t)o * BATCH + b;

    float a0 = 0.f, a1 = 0.f, a2 = 0.f, a3 = 0.f;
#pragma unroll
    for (int kzi = 0; kzi < SPLITS; kzi += 4) {
        a0 += p[(size_t)(kzi + 0) * (OUTF * BATCH)];
        a1 += p[(size_t)(kzi + 1) * (OUTF * BATCH)];
        a2 += p[(size_t)(kzi + 2) * (OUTF * BATCH)];
        a3 += p[(size_t)(kzi + 3) * (OUTF * BATCH)];
    }
    y[(size_t)b * OUTF + o] = (a0 + a1) + (a2 + a3);
}

// ---------------------------------------------------------------------------
extern "C" void kernel_launch(void* const* d_in, const int* in_sizes, int n_in,
                              void* d_out, int out_size)
{
    (void)in_sizes; (void)n_in; (void)out_size;
    const float* x          = (const float*)d_in[0];
    const float* weight     = (const float*)d_in[1];
    const float* align_conv = (const float*)d_in[2];
    const float* W_ih       = (const float*)d_in[3];
    // d_in[4] = W_hh : unused (h0 == 0)
    const float* b_ih       = (const float*)d_in[5];
    const float* b_hh       = (const float*)d_in[6];
    const float* W_att      = (const float*)d_in[7];
    const float* b_att      = (const float*)d_in[8];
    float* y = (float*)d_out;

    gate_kernel<<<BATCH, 256>>>(x, align_conv, W_ih, b_ih, b_hh, W_att, b_att);
    gemm_hmma<<<dim3(OUTF / 64, SPLITS), 256>>>(x, weight);
    reduce_kernel<<<(OUTF * BATCH) / 256, 256>>>(y);
}

// round 14
// speedup vs baseline: 1.3288x; 1.3288x over previous
#include <cuda_runtime.h>
#include <cuda_fp16.h>
#include <cstdint>
#include <cstddef>

#define BATCH 64
#define INF   1024
#define OUTF  1024
#define NEXP  8
#define HID   8
#define SPLITS 16

// c[e][b] = sum_f att[b,f] * align_conv[f,e]
__device__ float g_c[NEXP * BATCH];
// split-K RAW partials [kz][o][b] (4 MB static scratch); c applied in reduce
__device__ float g_part[SPLITS * OUTF * BATCH];

// ---------------------------------------------------------------------------
// arch-agnostic tensor-core helpers (sm_80+ PTX: valid at target sm_103)
// ---------------------------------------------------------------------------
__device__ __forceinline__ uint32_t smem_u32(const void* p) {
    uint32_t a;
    asm("{ .reg .u64 t; cvta.to.shared.u64 t, %1; cvt.u32.u64 %0, t; }"
        : "=r"(a) : "l"(p));
    return a;
}

__device__ __forceinline__ void ldsm4(uint32_t* r, uint32_t addr) {
    asm volatile("ldmatrix.sync.aligned.m8n8.x4.shared.b16 {%0,%1,%2,%3}, [%4];"
                 : "=r"(r[0]), "=r"(r[1]), "=r"(r[2]), "=r"(r[3]) : "r"(addr));
}

__device__ __forceinline__ void mma16816(float* d, const uint32_t* a,
                                         uint32_t b0, uint32_t b1) {
    asm volatile(
        "mma.sync.aligned.m16n8k16.row.col.f32.f16.f16.f32 "
        "{%0,%1,%2,%3}, {%4,%5,%6,%7}, {%8,%9}, {%0,%1,%2,%3};"
        : "+f"(d[0]), "+f"(d[1]), "+f"(d[2]), "+f"(d[3])
        : "r"(a[0]), "r"(a[1]), "r"(a[2]), "r"(a[3]), "r"(b0), "r"(b1));
}

__device__ __forceinline__ uint32_t h2bits(float a, float b) {
    __half2 h = __floats2half2_rn(a, b);   // low = a, high = b (k-order)
    return *reinterpret_cast<uint32_t*>(&h);
}

__device__ __forceinline__ float tanh_fast(float v) {
    float r;
    asm("tanh.approx.f32 %0, %1;" : "=f"(r) : "f"(v));
    return r;
}

// ---------------------------------------------------------------------------
// Gating: grid 64 (one block per batch sample), 256 threads.
// Runs CONCURRENTLY with the gemm (side stream); only reduce consumes g_c.
// ---------------------------------------------------------------------------
__global__ void __launch_bounds__(256) gate_kernel(
    const float* __restrict__ x,
    const float* __restrict__ align_conv,
    const float* __restrict__ W_ih,
    const float* __restrict__ b_ih,
    const float* __restrict__ b_hh,
    const float* __restrict__ W_att,
    const float* __restrict__ b_att)
{
    const int b   = blockIdx.x;
    const int tid = threadIdx.x;
    __shared__ float red[8];

    float4 v = ((const float4*)(x + (size_t)b * INF))[tid];
    float s = (v.x + v.y) + (v.z + v.w);
#pragma unroll
    for (int o = 16; o > 0; o >>= 1) s += __shfl_xor_sync(0xffffffffu, s, o);
    if ((tid & 31) == 0) red[tid >> 5] = s;
    __syncthreads();

    if (tid < 8) {
        float t8 = red[tid];
        t8 += __shfl_xor_sync(0xffu, t8, 1);
        t8 += __shfl_xor_sync(0xffu, t8, 2);
        t8 += __shfl_xor_sync(0xffu, t8, 4);
        const float pooled = t8 * (1.0f / INF);

        const int e = tid;
        float lg = b_att[e];
#pragma unroll
        for (int j = 0; j < HID; j++) {
            float rj = fmaxf(tanh_fast(pooled * W_ih[j] + b_ih[j] + b_hh[j]), 0.f);
            lg += rj * W_att[e * HID + j];
        }
        float mx = lg;
        mx = fmaxf(mx, __shfl_xor_sync(0xffu, mx, 1));
        mx = fmaxf(mx, __shfl_xor_sync(0xffu, mx, 2));
        mx = fmaxf(mx, __shfl_xor_sync(0xffu, mx, 4));
        float p = __expf(lg - mx);
        float ssum = p;
        ssum += __shfl_xor_sync(0xffu, ssum, 1);
        ssum += __shfl_xor_sync(0xffu, ssum, 2);
        ssum += __shfl_xor_sync(0xffu, ssum, 4);
        p /= ssum;

        float c = 0.f;
#pragma unroll
        for (int f = 0; f < NEXP; f++)
            c += __shfl_sync(0xffu, p, f) * align_conv[f * NEXP + e];
        g_c[e * BATCH + b] = c;
    }
}

// ---------------------------------------------------------------------------
// HMMA GEMM (R8-proven shape): part[kz][o][b] = sum_i w[e,o,i] * x[b,i]
//   (RAW partials — the gate coefficient is applied in the reduce.)
//   fp16 operands, fp32 accum (mma.sync m16n8k16).
//   CTA: M=128 (o), N=64 (b); grid = (8 o-tiles, 16 = 8 experts x 2 i-halves)
//   = 128 CTAs (single wave). K=512/CTA in 8 chunks of 64; double-buffered
//   24KB stages (48KB static). 128B rows + 16B XOR swizzle; warp tile m32xn32.
// ---------------------------------------------------------------------------
#define KC       64
#define NCH      8
#define A_BYTES  16384
#define STG      24576

__global__ void __launch_bounds__(256) gemm_hmma(const float* __restrict__ x,
                                                 const float* __restrict__ w)
{
    __shared__ __align__(16) uint8_t sm[2 * STG];
    const int tid = threadIdx.x;
    const int wid = tid >> 5;
    const int lid = tid & 31;
    const int o0  = blockIdx.x * 128;
    const int kz  = blockIdx.y;
    const int e   = kz >> 1;
    const int i0  = (kz & 1) * 512;

    const float* wbase = w + ((size_t)e << 20) + (size_t)o0 * INF + i0;
    const float* xbase = x + i0;

    const int m0 = (wid & 3) * 32;     // warp M offset
    const int n0 = (wid >> 2) * 32;    // warp N offset

    float d[2][4][4];
#pragma unroll
    for (int i = 0; i < 2; i++)
#pragma unroll
        for (int j = 0; j < 4; j++)
#pragma unroll
            for (int k = 0; k < 4; k++) d[i][j][k] = 0.f;

    float4 av[8], bv[4];
    const uint32_t smb = smem_u32(sm);

    // ---- prologue: load stage 0 ----
    {
        const float4* ws = (const float4*)wbase;
        const float4* xs = (const float4*)xbase;
#pragma unroll
        for (int r = 0; r < 8; r++) {
            int g = tid + (r << 8);
            av[r] = ws[(g >> 4) * 256 + (g & 15)];
        }
#pragma unroll
        for (int r = 0; r < 4; r++) {
            int g = tid + (r << 8);
            bv[r] = xs[(g >> 4) * 256 + (g & 15)];
        }
    }

#define STORE_STAGE(sidx) do {                                                 \
    uint8_t* stg = sm + (sidx) * STG;                                          \
    _Pragma("unroll")                                                          \
    for (int r = 0; r < 8; r++) {                                              \
        int g = tid + (r << 8);                                                \
        uint32_t off = (uint32_t)((g >> 4) * 128 + (g & 15) * 8);              \
        off ^= (off >> 3) & 0x70u;                                             \
        uint2 pv; pv.x = h2bits(av[r].x, av[r].y);                             \
        pv.y = h2bits(av[r].z, av[r].w);                                       \
        *(uint2*)(stg + off) = pv;                                             \
    }                                                                          \
    _Pragma("unroll")                                                          \
    for (int r = 0; r < 4; r++) {                                              \
        int g = tid + (r << 8);                                                \
        uint32_t off = (uint32_t)((g >> 4) * 128 + (g & 15) * 8);              \
        off ^= (off >> 3) & 0x70u;                                             \
        uint2 pv; pv.x = h2bits(bv[r].x, bv[r].y);                             \
        pv.y = h2bits(bv[r].z, bv[r].w);                                       \
        *(uint2*)(stg + A_BYTES + off) = pv;                                   \
    }                                                                          \
} while (0)

    STORE_STAGE(0);
    __syncthreads();

    for (int kc = 0; kc < NCH; kc++) {
        const int cur = kc & 1;

        if (kc + 1 < NCH) {
            const float4* ws = (const float4*)(wbase + (kc + 1) * KC);
            const float4* xs = (const float4*)(xbase + (kc + 1) * KC);
#pragma unroll
            for (int r = 0; r < 8; r++) {
                int g = tid + (r << 8);
                av[r] = ws[(g >> 4) * 256 + (g & 15)];
            }
#pragma unroll
            for (int r = 0; r < 4; r++) {
                int g = tid + (r << 8);
                bv[r] = xs[(g >> 4) * 256 + (g & 15)];
            }
        }

        // ---- compute on stage `cur` ----
        const uint32_t sb = smb + cur * STG;
#pragma unroll
        for (int ks = 0; ks < 4; ks++) {
            uint32_t afr[2][4], bfr[2][4];
#pragma unroll
            for (int mf = 0; mf < 2; mf++) {
                uint32_t row = (uint32_t)(m0 + mf * 16 + (lid & 15));
                uint32_t kg  = (uint32_t)(ks * 2 + (lid >> 4));
                uint32_t off = row * 128 + kg * 16;
                off ^= (off >> 3) & 0x70u;
                ldsm4(afr[mf], sb + off);
            }
#pragma unroll
            for (int nh = 0; nh < 2; nh++) {
                uint32_t nrow = (uint32_t)(n0 + nh * 16 + (lid & 7) + ((lid >> 4) << 3));
                uint32_t kg   = (uint32_t)(ks * 2 + ((lid >> 3) & 1));
                uint32_t off  = nrow * 128 + kg * 16;
                off ^= (off >> 3) & 0x70u;
                ldsm4(bfr[nh], sb + A_BYTES + off);
            }
#pragma unroll
            for (int mf = 0; mf < 2; mf++) {
                mma16816(d[mf][0], afr[mf], bfr[0][0], bfr[0][1]);
                mma16816(d[mf][1], afr[mf], bfr[0][2], bfr[0][3]);
                mma16816(d[mf][2], afr[mf], bfr[1][0], bfr[1][1]);
                mma16816(d[mf][3], afr[mf], bfr[1][2], bfr[1][3]);
            }
        }

        __syncthreads();
        if (kc + 1 < NCH) {
            STORE_STAGE(cur ^ 1);
            __syncthreads();
        }
    }

    // ---- epilogue: STG.64 raw partials to g_part[kz][o][b] ----
    float* part = g_part + (size_t)kz * (OUTF * BATCH);
    const int tg = lid >> 2;
    const int tc = (lid & 3) * 2;
#pragma unroll
    for (int mf = 0; mf < 2; mf++) {
#pragma unroll
        for (int nf = 0; nf < 4; nf++) {
            const int ol = m0 + mf * 16 + tg;
            const int bb = n0 + nf * 8 + tc;
            float2 v0; v0.x = d[mf][nf][0]; v0.y = d[mf][nf][1];
            float2 v1; v1.x = d[mf][nf][2]; v1.y = d[mf][nf][3];
            *(float2*)(part + (size_t)(o0 + ol) * BATCH + bb) = v0;
            *(float2*)(part + (size_t)(o0 + ol + 8) * BATCH + bb) = v1;
        }
    }
}

// ---------------------------------------------------------------------------
// Split-K reduce + gate apply + transpose:
//   y[b][o] = sum_kz c[b, e(kz)] * part[kz][o][b],  e(kz) = kz>>1.
// Coalesced loads (b fastest); 4 MB is L2-resident. g_c loads broadcast.
// ---------------------------------------------------------------------------
__global__ void __launch_bounds__(256) reduce_kernel(float* __restrict__ y)
{
    const int gid = blockIdx.x * 256 + threadIdx.x;   // 0..65535
    const int o = gid >> 6;
    const int b = gid & 63;
    const float* p = g_part + (size_t)o * BATCH + b;

    float cv[NEXP];
#pragma unroll
    for (int e = 0; e < NEXP; e++) cv[e] = g_c[e * BATCH + b];

    float a0 = 0.f, a1 = 0.f, a2 = 0.f, a3 = 0.f;
#pragma unroll
    for (int kzi = 0; kzi < SPLITS; kzi += 4) {
        a0 += cv[(kzi + 0) >> 1] * p[(size_t)(kzi + 0) * (OUTF * BATCH)];
        a1 += cv[(kzi + 1) >> 1] * p[(size_t)(kzi + 1) * (OUTF * BATCH)];
        a2 += cv[(kzi + 2) >> 1] * p[(size_t)(kzi + 2) * (OUTF * BATCH)];
        a3 += cv[(kzi + 3) >> 1] * p[(size_t)(kzi + 3) * (OUTF * BATCH)];
    }
    y[(size_t)b * OUTF + o] = (a0 + a1) + (a2 + a3);
}

// ---------------------------------------------------------------------------
extern "C" void kernel_launch(void* const* d_in, const int* in_sizes, int n_in,
                              void* d_out, int out_size)
{
    (void)in_sizes; (void)n_in; (void)out_size;
    const float* x          = (const float*)d_in[0];
    const float* weight     = (const float*)d_in[1];
    const float* align_conv = (const float*)d_in[2];
    const float* W_ih       = (const float*)d_in[3];
    // d_in[4] = W_hh : unused (h0 == 0)
    const float* b_ih       = (const float*)d_in[5];
    const float* b_hh       = (const float*)d_in[6];
    const float* W_att      = (const float*)d_in[7];
    const float* b_att      = (const float*)d_in[8];
    float* y = (float*)d_out;

    // One-time side stream + events (created on the uncaptured correctness
    // call; reused unchanged inside capture -> deterministic, no allocs).
    static cudaStream_t s_gate = nullptr;
    static cudaEvent_t  ev_fork = nullptr, ev_join = nullptr;
    if (s_gate == nullptr) {
        cudaStreamCreateWithFlags(&s_gate, cudaStreamNonBlocking);
        cudaEventCreateWithFlags(&ev_fork, cudaEventDisableTiming);
        cudaEventCreateWithFlags(&ev_join, cudaEventDisableTiming);
    }

    // fork: gate runs concurrently with the gemm (disjoint data, g_c only
    // consumed by reduce)
    cudaEventRecord(ev_fork, 0);
    cudaStreamWaitEvent(s_gate, ev_fork, 0);
    gate_kernel<<<BATCH, 256, 0, s_gate>>>(x, align_conv, W_ih, b_ih, b_hh,
                                           W_att, b_att);
    cudaEventRecord(ev_join, s_gate);

    gemm_hmma<<<dim3(OUTF / 128, SPLITS), 256>>>(x, weight);

    // join: reduce needs both g_part (stream 0) and g_c (side stream)
    cudaStreamWaitEvent(0, ev_join, 0);
    reduce_kernel<<<(OUTF * BATCH) / 256, 256>>>(y);
}